// round 16
// baseline (speedup 1.0000x reference)
#include <cuda_runtime.h>
#include <stddef.h>

// UniSAGE is fully linear. R16 = R15 forward pipeline (weights -> g0,g1;
// vertices -> scalars y0,yhat; 5 random ops/incidence) with k_final absorbed
// into k_gath: 391 gather blocks + 196 final blocks in ONE launch; final
// blocks spin (acquire) on a gather-done counter, then do the vertex sums.
// Graph: memset -> k_wyd -> k_scat -> k_gath_final  (4 nodes)

#define NV   100000
#define NE   200000
#define NNZt 800000
#define DIN  14
#define HID  128

#define BLK       256
#define NNZ_GRID  ((NNZt / 8 + BLK - 1) / BLK)    // 391
#define NNZ_THREADS (NNZt / 8)                     // 100000
#define VTX_GRID  ((NV / 2 + BLK - 1) / BLK)       // 196
#define WGRID     32
#define K1_GRID   (WGRID + NNZ_GRID + VTX_GRID)    // 619
#define GF_GRID   (NNZ_GRID + VTX_GRID)            // 587 (all co-resident)

// -------- device scratch (allocation-free), zeroed by one memset ----
struct __align__(16) Scratch {
    float4 vy[NV];   // {y0, yhat, deg, pad}
    float2 va[NV];   // {wraw = (B z0)_v, bzq = (B zq)_v}
    float4 ze[NE];   // {z0, zq, zh, edeg}
    float  acc[8];   // 0:edeg^T zh 1:zq^T edeg 2:Σy0 3:deg^T yh 4:Σq·wraw 5:Σq·wraw·bzq
    unsigned int tick;
    unsigned int wflag;      // weights ready
    unsigned int wbar_cnt;   // 32-block barrier (monotone)
    unsigned int wbar_phase;
    unsigned int wdone;      // w-chain stage-3 completion counter
    unsigned int gdone;      // gather-done counter
};
__device__ Scratch g_s;
__device__ float g_w[32];    // [0..13]=g0, [14..27]=g1, 28=d0, 29=d1, 30=cb1, 31=cb1'
__device__ float g_u1[256];
__device__ float g_u0[256];

__device__ __forceinline__ void red2(float2* a, float x, float y) {
    asm volatile("red.global.add.v2.f32 [%0], {%1,%2};" :: "l"(a), "f"(x), "f"(y) : "memory");
}
__device__ __forceinline__ void red4(float4* a, float x, float y, float z, float w) {
    asm volatile("red.global.add.v4.f32 [%0], {%1,%2,%3,%4};"
                 :: "l"(a), "f"(x), "f"(y), "f"(z), "f"(w) : "memory");
}
__device__ __forceinline__ void red1(float* a, float x) {
    asm volatile("red.global.add.f32 [%0], %1;" :: "l"(a), "f"(x) : "memory");
}
__device__ __forceinline__ unsigned ldacq(const unsigned* p) {
    unsigned v;
    asm volatile("ld.acquire.gpu.u32 %0, [%1];" : "=r"(v) : "l"(p));
    return v;
}

__device__ __forceinline__ float warp_dot128(const float* __restrict__ A,
                                             const float* __restrict__ B, int lane) {
    float s = 0.f;
#pragma unroll
    for (int k = 0; k < 4; k++) s += A[lane + 32 * k] * B[lane + 32 * k];
#pragma unroll
    for (int off = 16; off > 0; off >>= 1)
        s += __shfl_down_sync(0xffffffffu, s, off);
    return s;
}

__device__ __forceinline__ void wbar32(unsigned target) {
    __syncthreads();
    if (threadIdx.x == 0) {
        __threadfence();
        unsigned old = atomicAdd(&g_s.wbar_cnt, 1u);
        if (old == WGRID * target - 1) {
            atomicExch(&g_s.wbar_phase, target);
        } else {
            while (ldacq(&g_s.wbar_phase) < target) {}
        }
    }
    __syncthreads();
}

// ---- K1: fused w-chain + deg + y (proven R15 structure) ----
__global__ void __launch_bounds__(BLK)
k_wyd(const int* __restrict__ rows, const float* __restrict__ x0,
      const float* __restrict__ W0, const float* __restrict__ b0,
      const float* __restrict__ Wl0, const float* __restrict__ bl0,
      const float* __restrict__ Wl1, const float* __restrict__ bl1,
      const float* __restrict__ Wo0, const float* __restrict__ Wo1) {
    int bid = blockIdx.x;

    if (bid < WGRID) {
        int w = bid * 8 + (threadIdx.x >> 5);
        int lane = threadIdx.x & 31;
        int b = w >> 7, m = w & 127;
        const float* wo = b ? Wo1 : Wo0;

        float s = warp_dot128(Wl1 + m * HID, wo, lane);
        if (lane == 0) g_u1[w] = s;
        wbar32(1);

        s = warp_dot128(Wl0 + m * HID, g_u1 + b * HID, lane);
        if (lane == 0) g_u0[w] = s;
        wbar32(2);

        if (bid < 4) {
            int w3 = bid * 8 + (threadIdx.x >> 5);
            if (w3 < 28) {
                int b3 = w3 / DIN, m3 = w3 % DIN;
                float t = warp_dot128(W0 + m3 * HID, g_u0 + b3 * HID, lane);
                if (lane == 0) g_w[w3] = t;
            } else if (w3 < 30) {
                int b3 = w3 - 28;
                float t = 0.f;
#pragma unroll
                for (int k = 0; k < 4; k++) {
                    int h = lane + 32 * k;
                    t += b0[h] * g_u0[b3 * HID + h] + bl0[h] * g_u1[b3 * HID + h];
                }
#pragma unroll
                for (int off = 16; off > 0; off >>= 1)
                    t += __shfl_down_sync(0xffffffffu, t, off);
                if (lane == 0) g_w[28 + b3] = t;
            } else {
                int b3 = w3 - 30;
                const float* wo3 = b3 ? Wo1 : Wo0;
                float t = warp_dot128(bl1, wo3, lane);
                if (lane == 0) g_w[30 + b3] = t;
            }
            __syncthreads();
            if (threadIdx.x == 0) {
                __threadfence();
                unsigned old = atomicAdd(&g_s.wdone, 1u);
                if (old == 3) {
                    asm volatile("st.release.gpu.u32 [%0], %1;"
                                 :: "l"(&g_s.wflag), "r"(1u) : "memory");
                }
            }
        }
        return;
    }

    if (bid < WGRID + NNZ_GRID) {
        int t = (bid - WGRID) * BLK + threadIdx.x;
        if (t >= NNZ_THREADS) return;
        const int4* r4 = (const int4*)(rows) + t * 2;
        int4 r0 = r4[0], r1 = r4[1];
        red1(&g_s.vy[r0.x].z, 1.f); red1(&g_s.vy[r0.y].z, 1.f);
        red1(&g_s.vy[r0.z].z, 1.f); red1(&g_s.vy[r0.w].z, 1.f);
        red1(&g_s.vy[r1.x].z, 1.f); red1(&g_s.vy[r1.y].z, 1.f);
        red1(&g_s.vy[r1.z].z, 1.f); red1(&g_s.vy[r1.w].z, 1.f);
        return;
    }

    if (threadIdx.x == 0) {
        while (ldacq(&g_s.wflag) == 0) {}
    }
    __syncthreads();
    __shared__ float sg[32];
    if (threadIdx.x < 32) sg[threadIdx.x] = g_w[threadIdx.x];
    __syncthreads();

    int t = (bid - WGRID - NNZ_GRID) * BLK + threadIdx.x;
    if (t >= NV / 2) return;
    int v0 = 2 * t;
    const float4* xr = (const float4*)(x0 + (long long)v0 * DIN);
    float xs[28];
#pragma unroll
    for (int q = 0; q < 7; q++) {
        float4 f = xr[q];
        xs[q * 4 + 0] = f.x; xs[q * 4 + 1] = f.y;
        xs[q * 4 + 2] = f.z; xs[q * 4 + 3] = f.w;
    }
    float y0A = sg[28], yhA = sg[29], y0B = sg[28], yhB = sg[29];
#pragma unroll
    for (int j = 0; j < DIN; j++) {
        y0A += xs[j] * sg[j];
        yhA += xs[j] * sg[14 + j];
        y0B += xs[14 + j] * sg[j];
        yhB += xs[14 + j] * sg[14 + j];
    }
    *(float2*)&g_s.vy[v0]     = make_float2(y0A, yhA);
    *(float2*)&g_s.vy[v0 + 1] = make_float2(y0B, yhB);
}

// ---- P2: ze[e] += {y0[v], 1/deg[v], yhat[v], 1} — one red4 per incidence ----
__global__ void __launch_bounds__(BLK) k_scat(const int* __restrict__ rows,
                                              const int* __restrict__ cols) {
    int t = blockIdx.x * BLK + threadIdx.x;
    if (t >= NNZ_THREADS) return;
    const int4* r4 = (const int4*)(rows) + t * 2;
    const int4* c4 = (const int4*)(cols) + t * 2;
    int4 r0 = r4[0], r1 = r4[1];
    int4 c0 = c4[0], c1 = c4[1];
    float4 v0 = __ldcg(&g_s.vy[r0.x]), v1 = __ldcg(&g_s.vy[r0.y]);
    float4 v2 = __ldcg(&g_s.vy[r0.z]), v3 = __ldcg(&g_s.vy[r0.w]);
    float4 v4 = __ldcg(&g_s.vy[r1.x]), v5 = __ldcg(&g_s.vy[r1.y]);
    float4 v6 = __ldcg(&g_s.vy[r1.z]), v7 = __ldcg(&g_s.vy[r1.w]);
    red4(&g_s.ze[c0.x], v0.x, __fdividef(1.f, v0.z), v0.y, 1.f);
    red4(&g_s.ze[c0.y], v1.x, __fdividef(1.f, v1.z), v1.y, 1.f);
    red4(&g_s.ze[c0.z], v2.x, __fdividef(1.f, v2.z), v2.y, 1.f);
    red4(&g_s.ze[c0.w], v3.x, __fdividef(1.f, v3.z), v3.y, 1.f);
    red4(&g_s.ze[c1.x], v4.x, __fdividef(1.f, v4.z), v4.y, 1.f);
    red4(&g_s.ze[c1.y], v5.x, __fdividef(1.f, v5.z), v5.y, 1.f);
    red4(&g_s.ze[c1.z], v6.x, __fdividef(1.f, v6.z), v6.y, 1.f);
    red4(&g_s.ze[c1.w], v7.x, __fdividef(1.f, v7.z), v7.y, 1.f);
}

// ---- P3+P5 merged: blocks [0,391) gather; blocks [391,587) wait then final ----
__global__ void __launch_bounds__(BLK)
k_gath_final(const int* __restrict__ rows, const int* __restrict__ cols,
             const float* __restrict__ bo0, const float* __restrict__ bo1,
             float* __restrict__ out) {
    int bid = blockIdx.x;

    if (bid < NNZ_GRID) {
        // ---------- gather ----------
        int t = bid * BLK + threadIdx.x;
        float s_zh = 0.f, s_zq = 0.f;
        if (t < NNZ_THREADS) {
            const int4* r4 = (const int4*)(rows) + t * 2;
            const int4* c4 = (const int4*)(cols) + t * 2;
            int4 r0 = r4[0], r1 = r4[1];
            int4 c0 = c4[0], c1 = c4[1];
            float4 z0 = __ldcg(&g_s.ze[c0.x]), z1 = __ldcg(&g_s.ze[c0.y]);
            float4 z2 = __ldcg(&g_s.ze[c0.z]), z3 = __ldcg(&g_s.ze[c0.w]);
            float4 z4 = __ldcg(&g_s.ze[c1.x]), z5 = __ldcg(&g_s.ze[c1.y]);
            float4 z6 = __ldcg(&g_s.ze[c1.z]), z7 = __ldcg(&g_s.ze[c1.w]);
            red2(&g_s.va[r0.x], z0.x, z0.y);
            red2(&g_s.va[r0.y], z1.x, z1.y);
            red2(&g_s.va[r0.z], z2.x, z2.y);
            red2(&g_s.va[r0.w], z3.x, z3.y);
            red2(&g_s.va[r1.x], z4.x, z4.y);
            red2(&g_s.va[r1.y], z5.x, z5.y);
            red2(&g_s.va[r1.z], z6.x, z6.y);
            red2(&g_s.va[r1.w], z7.x, z7.y);
            s_zh = z0.z + z1.z + z2.z + z3.z + z4.z + z5.z + z6.z + z7.z;
            s_zq = z0.y + z1.y + z2.y + z3.y + z4.y + z5.y + z6.y + z7.y;
        }
#pragma unroll
        for (int off = 16; off > 0; off >>= 1) {
            s_zh += __shfl_down_sync(0xffffffffu, s_zh, off);
            s_zq += __shfl_down_sync(0xffffffffu, s_zq, off);
        }
        __shared__ float sh[16];
        int warp = threadIdx.x >> 5, lane = threadIdx.x & 31;
        if (lane == 0) { sh[warp] = s_zh; sh[8 + warp] = s_zq; }
        __syncthreads();
        if (threadIdx.x < 2) {
            float s = 0.f;
            for (int w = 0; w < 8; w++) s += sh[threadIdx.x * 8 + w];
            atomicAdd(&g_s.acc[threadIdx.x], s);
        }
        // signal done (after all reds in this block are visible)
        __syncthreads();
        if (threadIdx.x == 0) {
            __threadfence();
            atomicAdd(&g_s.gdone, 1u);
        }
        return;
    }

    // ---------- final: wait for all gather blocks ----------
    if (threadIdx.x == 0) {
        while (ldacq(&g_s.gdone) < NNZ_GRID) {}
    }
    __syncthreads();

    int t = (bid - NNZ_GRID) * BLK + threadIdx.x;
    float s0 = 0.f, s1 = 0.f, s2 = 0.f, s3 = 0.f;
    if (t < NV / 2) {
        int v0 = 2 * t;
        float4 a = g_s.vy[v0], b = g_s.vy[v0 + 1];
        float2 wa = g_s.va[v0], wb = g_s.va[v0 + 1];
        float qa = a.z > 0.f ? __fdividef(1.f, a.z) : 0.f;
        float qb = b.z > 0.f ? __fdividef(1.f, b.z) : 0.f;
        s0 = a.x + b.x;                               // Σ y0
        s1 = a.z * a.y + b.z * b.y;                   // deg^T yhat
        s2 = qa * wa.x + qb * wb.x;                   // 1^T P y0
        s3 = qa * wa.x * wa.y + qb * wb.x * wb.y;     // 1^T P² y0
    }
#pragma unroll
    for (int off = 16; off > 0; off >>= 1) {
        s0 += __shfl_down_sync(0xffffffffu, s0, off);
        s1 += __shfl_down_sync(0xffffffffu, s1, off);
        s2 += __shfl_down_sync(0xffffffffu, s2, off);
        s3 += __shfl_down_sync(0xffffffffu, s3, off);
    }
    __shared__ float sh2[32];
    int warp = threadIdx.x >> 5, lane = threadIdx.x & 31;
    if (lane == 0) { sh2[warp] = s0; sh2[8 + warp] = s1; sh2[16 + warp] = s2; sh2[24 + warp] = s3; }
    __syncthreads();
    if (threadIdx.x < 4) {
        float s = 0.f;
        for (int w = 0; w < 8; w++) s += sh2[threadIdx.x * 8 + w];
        atomicAdd(&g_s.acc[2 + threadIdx.x], s);
    }

    __threadfence();
    __shared__ unsigned int is_last;
    if (threadIdx.x == 0)
        is_last = (atomicInc(&g_s.tick, VTX_GRID - 1) == VTX_GRID - 1) ? 1u : 0u;
    __syncthreads();
    if (!is_last) return;
    __threadfence();

    if (threadIdx.x == 0) {
        float S_edeg_zh = g_s.acc[0];
        float S_zq_edeg = g_s.acc[1];
        float Sy0  = g_s.acc[2];
        float Sdyh = g_s.acc[3];
        float Sqw  = g_s.acc[4];
        float Sqwb = g_s.acc[5];
        float cb1  = g_w[30];
        float cb1p = g_w[31];
        float branch0 = (Sy0 + 2.f * Sqw + Sqwb + cb1 * ((float)NV + S_zq_edeg))
                        * (1.f / (float)NV) + bo0[0];
        float branch1 = (Sdyh + S_edeg_zh + cb1p * (float)NNZt)
                        * (1.f / (float)NE) + bo1[0];
        out[0] = branch0 + branch1;
    }
}

extern "C" void kernel_launch(void* const* d_in, const int* in_sizes, int n_in,
                              void* d_out, int out_size) {
    const float* x_0  = (const float*)d_in[0];
    const int*   rows = (const int*)d_in[2];
    const int*   cols = (const int*)d_in[3];
    const float* W0   = (const float*)d_in[4];
    const float* b0   = (const float*)d_in[5];
    const float* Wl0  = (const float*)d_in[8];
    const float* bl0  = (const float*)d_in[9];
    const float* Wl1  = (const float*)d_in[10];
    const float* bl1  = (const float*)d_in[11];
    const float* Wo0  = (const float*)d_in[12];
    const float* bo0  = (const float*)d_in[13];
    const float* Wo1  = (const float*)d_in[14];
    const float* bo1  = (const float*)d_in[15];
    float* out = (float*)d_out;

    void* p_s;
    cudaGetSymbolAddress(&p_s, g_s);
    cudaMemsetAsync(p_s, 0, sizeof(Scratch));

    k_wyd<<<K1_GRID, BLK>>>(rows, x_0, W0, b0, Wl0, bl0, Wl1, bl1, Wo0, Wo1);
    k_scat<<<NNZ_GRID, BLK>>>(rows, cols);
    k_gath_final<<<GF_GRID, BLK>>>(rows, cols, bo0, bo1, out);
}

// round 17
// speedup vs baseline: 1.1310x; 1.1310x over previous
#include <cuda_runtime.h>
#include <stddef.h>

// UniSAGE is fully linear. R17 = R15 skeleton (37.6us proven; R16 spin-merge
// regressed -> reverted) + ride-along reductions:
//   Σy0           -> k_wyd y-blocks (free, values in registers)
//   deg^T yhat    -> k_scat (vy already gathered)
//   1^T P y0      = Σ_inc z0·zq/edeg -> k_gath (ze already gathered)
//   edeg^T zh, zq^T edeg -> k_gath (already there)
// k_final shrinks to ONE coalesced term  s3 = Σ_v wraw·bzq/deg  at 391 blocks.
// Graph: memset -> k_wyd -> k_scat -> k_gath -> k_final  (5 nodes)

#define NV   100000
#define NE   200000
#define NNZt 800000
#define DIN  14
#define HID  128

#define BLK       256
#define NNZ_GRID  ((NNZt / 8 + BLK - 1) / BLK)    // 391
#define NNZ_THREADS (NNZt / 8)                     // 100000
#define VTX_GRID  ((NV / 2 + BLK - 1) / BLK)       // 196
#define FIN_GRID  ((NV + BLK - 1) / BLK)           // 391 (1 vertex/thread)
#define WGRID     32
#define K1_GRID   (WGRID + NNZ_GRID + VTX_GRID)    // 619

// -------- device scratch (allocation-free), zeroed by one memset ----
struct __align__(16) Scratch {
    float4 vy[NV];   // {y0, yhat, deg, pad}
    float2 va[NV];   // {wraw = (B z0)_v, bzq = (B zq)_v}
    float4 ze[NE];   // {z0, zq, zh, edeg}
    float  acc[8];   // 0:edeg^T zh 1:zq^T edeg 2:Σy0 3:deg^T yh 4:1^T P y0 5:1^T P² y0
    unsigned int tick;
    unsigned int wflag;
    unsigned int wbar_cnt;
    unsigned int wbar_phase;
    unsigned int wdone;
};
__device__ Scratch g_s;
__device__ float g_w[32];    // [0..13]=g0, [14..27]=g1, 28=d0, 29=d1, 30=cb1, 31=cb1'
__device__ float g_u1[256];
__device__ float g_u0[256];

__device__ __forceinline__ void red2(float2* a, float x, float y) {
    asm volatile("red.global.add.v2.f32 [%0], {%1,%2};" :: "l"(a), "f"(x), "f"(y) : "memory");
}
__device__ __forceinline__ void red4(float4* a, float x, float y, float z, float w) {
    asm volatile("red.global.add.v4.f32 [%0], {%1,%2,%3,%4};"
                 :: "l"(a), "f"(x), "f"(y), "f"(z), "f"(w) : "memory");
}
__device__ __forceinline__ void red1(float* a, float x) {
    asm volatile("red.global.add.f32 [%0], %1;" :: "l"(a), "f"(x) : "memory");
}
__device__ __forceinline__ unsigned ldacq(const unsigned* p) {
    unsigned v;
    asm volatile("ld.acquire.gpu.u32 %0, [%1];" : "=r"(v) : "l"(p));
    return v;
}

__device__ __forceinline__ float warp_dot128(const float* __restrict__ A,
                                             const float* __restrict__ B, int lane) {
    float s = 0.f;
#pragma unroll
    for (int k = 0; k < 4; k++) s += A[lane + 32 * k] * B[lane + 32 * k];
#pragma unroll
    for (int off = 16; off > 0; off >>= 1)
        s += __shfl_down_sync(0xffffffffu, s, off);
    return s;
}

__device__ __forceinline__ void wbar32(unsigned target) {
    __syncthreads();
    if (threadIdx.x == 0) {
        __threadfence();
        unsigned old = atomicAdd(&g_s.wbar_cnt, 1u);
        if (old == WGRID * target - 1) {
            atomicExch(&g_s.wbar_phase, target);
        } else {
            while (ldacq(&g_s.wbar_phase) < target) {}
        }
    }
    __syncthreads();
}

// block-reduce one value and atomically add to *dst (256 threads)
__device__ __forceinline__ void block_acc1(float v, float* dst) {
#pragma unroll
    for (int off = 16; off > 0; off >>= 1)
        v += __shfl_down_sync(0xffffffffu, v, off);
    __shared__ float sh[8];
    int warp = threadIdx.x >> 5, lane = threadIdx.x & 31;
    if (lane == 0) sh[warp] = v;
    __syncthreads();
    if (threadIdx.x == 0) {
        float s = 0.f;
#pragma unroll
        for (int w = 0; w < 8; w++) s += sh[w];
        atomicAdd(dst, s);
    }
}

// ---- K1: fused w-chain + deg + y (+ Σy0 ride) ----
__global__ void __launch_bounds__(BLK)
k_wyd(const int* __restrict__ rows, const float* __restrict__ x0,
      const float* __restrict__ W0, const float* __restrict__ b0,
      const float* __restrict__ Wl0, const float* __restrict__ bl0,
      const float* __restrict__ Wl1, const float* __restrict__ bl1,
      const float* __restrict__ Wo0, const float* __restrict__ Wo1) {
    int bid = blockIdx.x;

    if (bid < WGRID) {
        int w = bid * 8 + (threadIdx.x >> 5);
        int lane = threadIdx.x & 31;
        int b = w >> 7, m = w & 127;
        const float* wo = b ? Wo1 : Wo0;

        float s = warp_dot128(Wl1 + m * HID, wo, lane);
        if (lane == 0) g_u1[w] = s;
        wbar32(1);

        s = warp_dot128(Wl0 + m * HID, g_u1 + b * HID, lane);
        if (lane == 0) g_u0[w] = s;
        wbar32(2);

        if (bid < 4) {
            int w3 = bid * 8 + (threadIdx.x >> 5);
            if (w3 < 28) {
                int b3 = w3 / DIN, m3 = w3 % DIN;
                float t = warp_dot128(W0 + m3 * HID, g_u0 + b3 * HID, lane);
                if (lane == 0) g_w[w3] = t;
            } else if (w3 < 30) {
                int b3 = w3 - 28;
                float t = 0.f;
#pragma unroll
                for (int k = 0; k < 4; k++) {
                    int h = lane + 32 * k;
                    t += b0[h] * g_u0[b3 * HID + h] + bl0[h] * g_u1[b3 * HID + h];
                }
#pragma unroll
                for (int off = 16; off > 0; off >>= 1)
                    t += __shfl_down_sync(0xffffffffu, t, off);
                if (lane == 0) g_w[28 + b3] = t;
            } else {
                int b3 = w3 - 30;
                const float* wo3 = b3 ? Wo1 : Wo0;
                float t = warp_dot128(bl1, wo3, lane);
                if (lane == 0) g_w[30 + b3] = t;
            }
            __syncthreads();
            if (threadIdx.x == 0) {
                __threadfence();
                unsigned old = atomicAdd(&g_s.wdone, 1u);
                if (old == 3) {
                    asm volatile("st.release.gpu.u32 [%0], %1;"
                                 :: "l"(&g_s.wflag), "r"(1u) : "memory");
                }
            }
        }
        return;
    }

    if (bid < WGRID + NNZ_GRID) {
        int t = (bid - WGRID) * BLK + threadIdx.x;
        if (t >= NNZ_THREADS) return;
        const int4* r4 = (const int4*)(rows) + t * 2;
        int4 r0 = r4[0], r1 = r4[1];
        red1(&g_s.vy[r0.x].z, 1.f); red1(&g_s.vy[r0.y].z, 1.f);
        red1(&g_s.vy[r0.z].z, 1.f); red1(&g_s.vy[r0.w].z, 1.f);
        red1(&g_s.vy[r1.x].z, 1.f); red1(&g_s.vy[r1.y].z, 1.f);
        red1(&g_s.vy[r1.z].z, 1.f); red1(&g_s.vy[r1.w].z, 1.f);
        return;
    }

    // ---- y-compute (+ Σy0 ride) ----
    if (threadIdx.x == 0) {
        while (ldacq(&g_s.wflag) == 0) {}
    }
    __syncthreads();
    __shared__ float sg[32];
    if (threadIdx.x < 32) sg[threadIdx.x] = g_w[threadIdx.x];
    __syncthreads();

    int t = (bid - WGRID - NNZ_GRID) * BLK + threadIdx.x;
    float sy0 = 0.f;
    if (t < NV / 2) {
        int v0 = 2 * t;
        const float4* xr = (const float4*)(x0 + (long long)v0 * DIN);
        float xs[28];
#pragma unroll
        for (int q = 0; q < 7; q++) {
            float4 f = xr[q];
            xs[q * 4 + 0] = f.x; xs[q * 4 + 1] = f.y;
            xs[q * 4 + 2] = f.z; xs[q * 4 + 3] = f.w;
        }
        float y0A = sg[28], yhA = sg[29], y0B = sg[28], yhB = sg[29];
#pragma unroll
        for (int j = 0; j < DIN; j++) {
            y0A += xs[j] * sg[j];
            yhA += xs[j] * sg[14 + j];
            y0B += xs[14 + j] * sg[j];
            yhB += xs[14 + j] * sg[14 + j];
        }
        *(float2*)&g_s.vy[v0]     = make_float2(y0A, yhA);   // .z red'd concurrently
        *(float2*)&g_s.vy[v0 + 1] = make_float2(y0B, yhB);
        sy0 = y0A + y0B;
    }
    block_acc1(sy0, &g_s.acc[2]);      // Σ y0
}

// ---- P2: ze[e] += {y0, 1/deg, yhat, 1}  (+ deg^T yhat ride) ----
__global__ void __launch_bounds__(BLK) k_scat(const int* __restrict__ rows,
                                              const int* __restrict__ cols) {
    int t = blockIdx.x * BLK + threadIdx.x;
    float syh = 0.f;
    if (t < NNZ_THREADS) {
        const int4* r4 = (const int4*)(rows) + t * 2;
        const int4* c4 = (const int4*)(cols) + t * 2;
        int4 r0 = r4[0], r1 = r4[1];
        int4 c0 = c4[0], c1 = c4[1];
        float4 v0 = __ldcg(&g_s.vy[r0.x]), v1 = __ldcg(&g_s.vy[r0.y]);
        float4 v2 = __ldcg(&g_s.vy[r0.z]), v3 = __ldcg(&g_s.vy[r0.w]);
        float4 v4 = __ldcg(&g_s.vy[r1.x]), v5 = __ldcg(&g_s.vy[r1.y]);
        float4 v6 = __ldcg(&g_s.vy[r1.z]), v7 = __ldcg(&g_s.vy[r1.w]);
        red4(&g_s.ze[c0.x], v0.x, __fdividef(1.f, v0.z), v0.y, 1.f);
        red4(&g_s.ze[c0.y], v1.x, __fdividef(1.f, v1.z), v1.y, 1.f);
        red4(&g_s.ze[c0.z], v2.x, __fdividef(1.f, v2.z), v2.y, 1.f);
        red4(&g_s.ze[c0.w], v3.x, __fdividef(1.f, v3.z), v3.y, 1.f);
        red4(&g_s.ze[c1.x], v4.x, __fdividef(1.f, v4.z), v4.y, 1.f);
        red4(&g_s.ze[c1.y], v5.x, __fdividef(1.f, v5.z), v5.y, 1.f);
        red4(&g_s.ze[c1.z], v6.x, __fdividef(1.f, v6.z), v6.y, 1.f);
        red4(&g_s.ze[c1.w], v7.x, __fdividef(1.f, v7.z), v7.y, 1.f);
        syh = v0.y + v1.y + v2.y + v3.y + v4.y + v5.y + v6.y + v7.y;  // Σ_inc yhat[row] = deg^T yh
    }
    block_acc1(syh, &g_s.acc[3]);
}

// ---- P3: va[v] += {z0, zq}; rides: edeg^T zh, zq^T edeg, Σ_e z0·zq ----
__global__ void __launch_bounds__(BLK) k_gath(const int* __restrict__ rows,
                                              const int* __restrict__ cols) {
    int t = blockIdx.x * BLK + threadIdx.x;
    float s_zh = 0.f, s_zq = 0.f, s_pz = 0.f;
    if (t < NNZ_THREADS) {
        const int4* r4 = (const int4*)(rows) + t * 2;
        const int4* c4 = (const int4*)(cols) + t * 2;
        int4 r0 = r4[0], r1 = r4[1];
        int4 c0 = c4[0], c1 = c4[1];
        float4 z0 = __ldcg(&g_s.ze[c0.x]), z1 = __ldcg(&g_s.ze[c0.y]);
        float4 z2 = __ldcg(&g_s.ze[c0.z]), z3 = __ldcg(&g_s.ze[c0.w]);
        float4 z4 = __ldcg(&g_s.ze[c1.x]), z5 = __ldcg(&g_s.ze[c1.y]);
        float4 z6 = __ldcg(&g_s.ze[c1.z]), z7 = __ldcg(&g_s.ze[c1.w]);
        red2(&g_s.va[r0.x], z0.x, z0.y);
        red2(&g_s.va[r0.y], z1.x, z1.y);
        red2(&g_s.va[r0.z], z2.x, z2.y);
        red2(&g_s.va[r0.w], z3.x, z3.y);
        red2(&g_s.va[r1.x], z4.x, z4.y);
        red2(&g_s.va[r1.y], z5.x, z5.y);
        red2(&g_s.va[r1.z], z6.x, z6.y);
        red2(&g_s.va[r1.w], z7.x, z7.y);
        s_zh = z0.z + z1.z + z2.z + z3.z + z4.z + z5.z + z6.z + z7.z;
        s_zq = z0.y + z1.y + z2.y + z3.y + z4.y + z5.y + z6.y + z7.y;
        // Σ_e z0·zq: each edge seen edeg times -> divide by edeg (z.w >= 1 here)
        s_pz = __fdividef(z0.x * z0.y, z0.w) + __fdividef(z1.x * z1.y, z1.w)
             + __fdividef(z2.x * z2.y, z2.w) + __fdividef(z3.x * z3.y, z3.w)
             + __fdividef(z4.x * z4.y, z4.w) + __fdividef(z5.x * z5.y, z5.w)
             + __fdividef(z6.x * z6.y, z6.w) + __fdividef(z7.x * z7.y, z7.w);
    }
#pragma unroll
    for (int off = 16; off > 0; off >>= 1) {
        s_zh += __shfl_down_sync(0xffffffffu, s_zh, off);
        s_zq += __shfl_down_sync(0xffffffffu, s_zq, off);
        s_pz += __shfl_down_sync(0xffffffffu, s_pz, off);
    }
    __shared__ float sh[24];
    int warp = threadIdx.x >> 5, lane = threadIdx.x & 31;
    if (lane == 0) { sh[warp] = s_zh; sh[8 + warp] = s_zq; sh[16 + warp] = s_pz; }
    __syncthreads();
    if (threadIdx.x < 3) {
        float s = 0.f;
        for (int w = 0; w < 8; w++) s += sh[threadIdx.x * 8 + w];
        if (threadIdx.x < 2) atomicAdd(&g_s.acc[threadIdx.x], s);
        else                 atomicAdd(&g_s.acc[4], s);           // 1^T P y0
    }
}

// ---- P5: ONLY s3 = Σ_v wraw·bzq/deg + scalar combine (ticket) ----
__global__ void __launch_bounds__(BLK)
k_final(const float* __restrict__ bo0, const float* __restrict__ bo1,
        float* __restrict__ out) {
    int t = blockIdx.x * BLK + threadIdx.x;
    float s3 = 0.f;
    if (t < NV) {
        float4 a = g_s.vy[t];
        float2 w = g_s.va[t];
        if (a.z > 0.f) s3 = __fdividef(w.x * w.y, a.z);
    }
    block_acc1(s3, &g_s.acc[5]);

    __threadfence();
    __shared__ unsigned int is_last;
    if (threadIdx.x == 0)
        is_last = (atomicInc(&g_s.tick, gridDim.x - 1) == gridDim.x - 1) ? 1u : 0u;
    __syncthreads();
    if (!is_last) return;
    __threadfence();

    if (threadIdx.x == 0) {
        float S_edeg_zh = g_s.acc[0];
        float S_zq_edeg = g_s.acc[1];
        float Sy0  = g_s.acc[2];
        float Sdyh = g_s.acc[3];
        float Sqw  = g_s.acc[4];
        float Sqwb = g_s.acc[5];
        float cb1  = g_w[30];
        float cb1p = g_w[31];
        float branch0 = (Sy0 + 2.f * Sqw + Sqwb + cb1 * ((float)NV + S_zq_edeg))
                        * (1.f / (float)NV) + bo0[0];
        float branch1 = (Sdyh + S_edeg_zh + cb1p * (float)NNZt)
                        * (1.f / (float)NE) + bo1[0];
        out[0] = branch0 + branch1;
    }
}

extern "C" void kernel_launch(void* const* d_in, const int* in_sizes, int n_in,
                              void* d_out, int out_size) {
    const float* x_0  = (const float*)d_in[0];
    const int*   rows = (const int*)d_in[2];
    const int*   cols = (const int*)d_in[3];
    const float* W0   = (const float*)d_in[4];
    const float* b0   = (const float*)d_in[5];
    const float* Wl0  = (const float*)d_in[8];
    const float* bl0  = (const float*)d_in[9];
    const float* Wl1  = (const float*)d_in[10];
    const float* bl1  = (const float*)d_in[11];
    const float* Wo0  = (const float*)d_in[12];
    const float* bo0  = (const float*)d_in[13];
    const float* Wo1  = (const float*)d_in[14];
    const float* bo1  = (const float*)d_in[15];
    float* out = (float*)d_out;

    void* p_s;
    cudaGetSymbolAddress(&p_s, g_s);
    cudaMemsetAsync(p_s, 0, sizeof(Scratch));

    k_wyd<<<K1_GRID, BLK>>>(rows, x_0, W0, b0, Wl0, bl0, Wl1, bl1, Wo0, Wo1);
    k_scat<<<NNZ_GRID, BLK>>>(rows, cols);
    k_gath<<<NNZ_GRID, BLK>>>(rows, cols);
    k_final<<<FIN_GRID, BLK>>>(bo0, bo1, out);
}